// round 5
// baseline (speedup 1.0000x reference)
#include <cuda_runtime.h>
#include <math.h>

#define VOC    50257
#define EMB    128
#define N_MEM  8192
#define T_Q    50
#define T_M    50
#define N_HOPS 3

#define NBV  148                 // blocks for VOC-streaming kernels
#define TBV  1024
#define NWV  (NBV * (TBV / 32))  // 4736 warps

#define NBM  128                 // blocks for memory-space kernel
#define TBM  64

#define SHIFT 24.0f              // constant softmax shift (cancels exactly)

// ---------------- scratch ----------------
__device__ float g_u[EMB];
__device__ float g_pv[VOC + 4];      // u . Wa[v]  (+pad for float4 tail store)
__device__ float g_sTA[N_MEM];       // u . TA[n]
__device__ float g_cw[VOC];          // summed attn weight per vocab token
__device__ float g_wo[EMB];          // weighted_out numerator
__device__ float g_den;              // softmax denominator (times e^-SHIFT)
__device__ float g_plmax[NBV];
__device__ float g_plden[NBV];
__device__ unsigned g_ctr_wo;        // last-block counters (reset by consumer)
__device__ unsigned g_ctr_lg;

__device__ __forceinline__ float dot4(float4 a, float4 b) {
    return fmaf(a.x, b.x, fmaf(a.y, b.y, fmaf(a.z, b.z, a.w * b.w)));
}
__device__ __forceinline__ float warp_sum(float p) {
#pragma unroll
    for (int o = 16; o; o >>= 1) p += __shfl_xor_sync(0xFFFFFFFFu, p, o);
    return p;
}

// ---------------- u0 = sum_t Wb[query[t]] ----------------
__global__ void k_u0(const int* __restrict__ q, const float* __restrict__ Wb) {
    int e = threadIdx.x;
    float a = 0.f;
#pragma unroll 10
    for (int t = 0; t < T_Q; t++) a += Wb[(long)__ldg(q + t) * EMB + e];
    g_u[e] = a;
}

// ---------------- pv[v] = u.Wa[v]; sTA[n] = u.TA[n]; zero cw/wo/den ----------------
__global__ void k_pv(const float* __restrict__ Wa, const float* __restrict__ TA) {
    __shared__ float4 su4[32];
    int tid = threadIdx.x, lane = tid & 31, wid = tid >> 5;
    int gid = blockIdx.x * TBV + tid;
    if (gid < VOC) g_cw[gid] = 0.f;
    if (blockIdx.x == 0) {
        if (tid < EMB) g_wo[tid] = 0.f;
        if (tid == EMB) g_den = 0.f;
    }
    if (tid < 32) su4[tid] = ((const float4*)g_u)[tid];
    __syncthreads();
    float4 uu = su4[lane];
    int gw = blockIdx.x * 32 + wid;

    const float4 Z = make_float4(0.f, 0.f, 0.f, 0.f);
    for (long r0 = (long)gw * 4; r0 < VOC; r0 += (long)NWV * 4) {
        const float4* a = (const float4*)(Wa + r0 * EMB);
        bool b1 = r0 + 1 < VOC, b2 = r0 + 2 < VOC, b3 = r0 + 3 < VOC;
        float4 v0 = a[lane];
        float4 v1 = b1 ? a[32 + lane] : Z;
        float4 v2 = b2 ? a[64 + lane] : Z;
        float4 v3 = b3 ? a[96 + lane] : Z;
        float p0 = dot4(v0, uu), p1 = dot4(v1, uu), p2 = dot4(v2, uu), p3 = dot4(v3, uu);
#pragma unroll
        for (int o = 16; o; o >>= 1) {
            p0 += __shfl_xor_sync(0xFFFFFFFFu, p0, o);
            p1 += __shfl_xor_sync(0xFFFFFFFFu, p1, o);
            p2 += __shfl_xor_sync(0xFFFFFFFFu, p2, o);
            p3 += __shfl_xor_sync(0xFFFFFFFFu, p3, o);
        }
        if (lane == 0)
            *((float4*)(g_pv + r0)) = make_float4(p0, p1, p2, p3);  // padded tail
    }
    for (long r0 = (long)gw * 4; r0 < N_MEM; r0 += (long)NWV * 4) {
        const float4* a = (const float4*)(TA + r0 * EMB);
        float4 v0 = a[lane], v1 = a[32 + lane], v2 = a[64 + lane], v3 = a[96 + lane];
        float p0 = dot4(v0, uu), p1 = dot4(v1, uu), p2 = dot4(v2, uu), p3 = dot4(v3, uu);
#pragma unroll
        for (int o = 16; o; o >>= 1) {
            p0 += __shfl_xor_sync(0xFFFFFFFFu, p0, o);
            p1 += __shfl_xor_sync(0xFFFFFFFFu, p1, o);
            p2 += __shfl_xor_sync(0xFFFFFFFFu, p2, o);
            p3 += __shfl_xor_sync(0xFFFFFFFFu, p3, o);
        }
        if (lane == 0)
            *((float4*)(g_sTA + r0)) = make_float4(p0, p1, p2, p3);
    }
}

// ---------------- per-memory: score gather, w=exp, denom, scatter cw, w*TC ----------------
__global__ void k_hopmem(const int* __restrict__ story, const float* __restrict__ TC) {
    __shared__ int   sst[TBM * T_M];
    __shared__ float sw[TBM];
    __shared__ float sred[TBM / 32];
    __shared__ float sacc[TBM / 32][EMB];
    int tid = threadIdx.x, lane = tid & 31, wid = tid >> 5;

    long base = (long)blockIdx.x * TBM * T_M;
#pragma unroll 4
    for (int i = tid; i < TBM * T_M; i += TBM) sst[i] = story[base + i];
    __syncthreads();

    int n = blockIdx.x * TBM + tid;
    float s = g_sTA[n];
#pragma unroll 10
    for (int t = 0; t < T_M; t++) s += g_pv[sst[tid * T_M + t]];
    float w = __expf(s - SHIFT);
    sw[tid] = w;

    float d = warp_sum(w);
    if (lane == 0) sred[wid] = d;

#pragma unroll 10
    for (int t = 0; t < T_M; t++) atomicAdd(&g_cw[sst[tid * T_M + t]], w);
    __syncthreads();

    if (tid == 0) {
        float db = 0.f;
#pragma unroll
        for (int i = 0; i < TBM / 32; i++) db += sred[i];
        atomicAdd(&g_den, db);
    }

    float4 acc = make_float4(0.f, 0.f, 0.f, 0.f);
    for (int j = wid; j < TBM; j += TBM / 32) {
        float wn = sw[j];
        float4 v = ((const float4*)(TC + (long)(blockIdx.x * TBM + j) * EMB))[lane];
        acc.x += wn * v.x; acc.y += wn * v.y; acc.z += wn * v.z; acc.w += wn * v.w;
    }
    sacc[wid][lane * 4 + 0] = acc.x;
    sacc[wid][lane * 4 + 1] = acc.y;
    sacc[wid][lane * 4 + 2] = acc.z;
    sacc[wid][lane * 4 + 3] = acc.w;
    __syncthreads();
    if (tid < EMB / 2) {
#pragma unroll
        for (int k = 0; k < 2; k++) {
            int e = tid * 2 + k;
            float v = 0.f;
#pragma unroll
            for (int w2 = 0; w2 < TBM / 32; w2++) v += sacc[w2][e];
            atomicAdd(&g_wo[e], v);
        }
    }
}

// ---------------- wo += sum_v cw[v]*Wc[v]; last block does gated update ----------------
__global__ void k_wo(const float* __restrict__ Wc,
                     const float* __restrict__ Wt_w, const float* __restrict__ Wt_b,
                     const float* __restrict__ H_w,  const float* __restrict__ H_b) {
    __shared__ float sacc[32][EMB];   // 16 KB
    __shared__ int slast;
    int tid = threadIdx.x, lane = tid & 31, wid = tid >> 5;

    float4 acc = make_float4(0.f, 0.f, 0.f, 0.f);
    int gw = blockIdx.x * 32 + wid;
    for (long r0 = (long)gw * 4; r0 < VOC; r0 += (long)NWV * 4) {
        const float4* a = (const float4*)(Wc + r0 * EMB);
        bool b1 = r0 + 1 < VOC, b2 = r0 + 2 < VOC, b3 = r0 + 3 < VOC;
        float c0 = g_cw[r0];
        float c1 = b1 ? g_cw[r0 + 1] : 0.f;
        float c2 = b2 ? g_cw[r0 + 2] : 0.f;
        float c3 = b3 ? g_cw[r0 + 3] : 0.f;
        float4 v0 = a[lane];
        float4 v1 = b1 ? a[32 + lane] : v0;
        float4 v2 = b2 ? a[64 + lane] : v0;
        float4 v3 = b3 ? a[96 + lane] : v0;
        acc.x += c0 * v0.x + c1 * v1.x + c2 * v2.x + c3 * v3.x;
        acc.y += c0 * v0.y + c1 * v1.y + c2 * v2.y + c3 * v3.y;
        acc.z += c0 * v0.z + c1 * v1.z + c2 * v2.z + c3 * v3.z;
        acc.w += c0 * v0.w + c1 * v1.w + c2 * v2.w + c3 * v3.w;
    }
    sacc[wid][lane * 4 + 0] = acc.x;
    sacc[wid][lane * 4 + 1] = acc.y;
    sacc[wid][lane * 4 + 2] = acc.z;
    sacc[wid][lane * 4 + 3] = acc.w;
    __syncthreads();
    if (tid < EMB) {
        float v = 0.f;
#pragma unroll
        for (int w2 = 0; w2 < 32; w2++) v += sacc[w2][tid];
        atomicAdd(&g_wo[tid], v);
    }
    __threadfence();
    if (tid == 0) slast = (atomicAdd(&g_ctr_wo, 1u) == (unsigned)(gridDim.x - 1));
    __syncthreads();
    if (!slast) return;

    // ---- last block: gated update of u ----
    __shared__ __align__(16) float su[EMB], swo[EMB], sdd[2 * EMB];
    if (tid < EMB) {
        su[tid]  = g_u[tid];
        swo[tid] = g_wo[tid] / g_den;
    }
    __syncthreads();
    {
        int rr0 = wid * 8;                       // 32 warps x 8 rows = 256 dots
#pragma unroll 2
        for (int j = 0; j < 8; j++) {
            int rr = rr0 + j;
            const float* W   = (rr < EMB) ? (Wt_w + (long)rr * EMB) : (H_w + (long)(rr - EMB) * EMB);
            const float* vec = (rr < EMB) ? su : swo;
            float p = warp_sum(dot4(((const float4*)W)[lane], ((const float4*)vec)[lane]));
            if (lane == 0) sdd[rr] = p;
        }
    }
    __syncthreads();
    if (tid < EMB) {
        float t = 1.f / (1.f + __expf(-(sdd[tid] + Wt_b[tid])));
        g_u[tid] = su[tid] * (1.f - t) + (sdd[EMB + tid] + H_b[tid]) * t;
    }
    if (tid == 0) g_ctr_wo = 0u;
}

// ---------------- logits + online partials; last block combines + normalizes ----------------
__global__ void k_logits(const float* __restrict__ wout, float* __restrict__ out) {
    __shared__ float4 su4[32];
    __shared__ float sm[32], sd[32];
    __shared__ int slast;
    __shared__ float sc;
    int tid = threadIdx.x, lane = tid & 31, wid = tid >> 5;
    if (tid < 32) su4[tid] = ((const float4*)g_u)[tid];
    __syncthreads();
    float4 uu = su4[lane];

    float m = -INFINITY, d = 0.f;
    int gw = blockIdx.x * 32 + wid;
    for (long r0 = (long)gw * 4; r0 < VOC; r0 += (long)NWV * 4) {
        const float4* a = (const float4*)(wout + r0 * EMB);
        bool b1 = r0 + 1 < VOC, b2 = r0 + 2 < VOC, b3 = r0 + 3 < VOC;
        float4 v0 = a[lane];
        float4 v1 = b1 ? a[32 + lane] : v0;
        float4 v2 = b2 ? a[64 + lane] : v0;
        float4 v3 = b3 ? a[96 + lane] : v0;
        float p0 = dot4(v0, uu), p1 = dot4(v1, uu), p2 = dot4(v2, uu), p3 = dot4(v3, uu);
#pragma unroll
        for (int o = 16; o; o >>= 1) {
            p0 += __shfl_xor_sync(0xFFFFFFFFu, p0, o);
            p1 += __shfl_xor_sync(0xFFFFFFFFu, p1, o);
            p2 += __shfl_xor_sync(0xFFFFFFFFu, p2, o);
            p3 += __shfl_xor_sync(0xFFFFFFFFu, p3, o);
        }
        if (lane == 0) {
            if (b3) *((float4*)(out + r0)) = make_float4(p0, p1, p2, p3);
            else {
                out[r0] = p0;
                if (b1) out[r0 + 1] = p1;
                if (b2) out[r0 + 2] = p2;
            }
        }
        float mn = fmaxf(m, p0);
        d = d * __expf(m - mn) + __expf(p0 - mn); m = mn;
        if (b1) { mn = fmaxf(m, p1); d = d * __expf(m - mn) + __expf(p1 - mn); m = mn; }
        if (b2) { mn = fmaxf(m, p2); d = d * __expf(m - mn) + __expf(p2 - mn); m = mn; }
        if (b3) { mn = fmaxf(m, p3); d = d * __expf(m - mn) + __expf(p3 - mn); m = mn; }
    }
    if (lane == 0) { sm[wid] = m; sd[wid] = d; }
    __syncthreads();
    if (tid < 32) {
        float mm = sm[tid], dd = sd[tid];
#pragma unroll
        for (int o = 16; o; o >>= 1) {
            float mo  = __shfl_xor_sync(0xFFFFFFFFu, mm, o);
            float ddo = __shfl_xor_sync(0xFFFFFFFFu, dd, o);
            float mn  = fmaxf(mm, mo);
            dd = dd * __expf(mm - mn) + ddo * __expf(mo - mn);
            mm = mn;
        }
        if (tid == 0) { g_plmax[blockIdx.x] = mm; g_plden[blockIdx.x] = dd; }
    }
    __threadfence();
    if (tid == 0) slast = (atomicAdd(&g_ctr_lg, 1u) == (unsigned)(gridDim.x - 1));
    __syncthreads();
    if (!slast) return;

    // ---- last block: combine partials, normalize out ----
    if (tid < 32) {
        float mm = -INFINITY, dd = 0.f;
        for (int b = tid; b < NBV; b += 32) {
            float mo = g_plmax[b], ddo = g_plden[b];
            float mn = fmaxf(mm, mo);
            dd = dd * __expf(mm - mn) + ddo * __expf(mo - mn);
            mm = mn;
        }
#pragma unroll
        for (int o = 16; o; o >>= 1) {
            float mo  = __shfl_xor_sync(0xFFFFFFFFu, mm, o);
            float ddo = __shfl_xor_sync(0xFFFFFFFFu, dd, o);
            float mn  = fmaxf(mm, mo);
            dd = dd * __expf(mm - mn) + ddo * __expf(mo - mn);
            mm = mn;
        }
        if (tid == 0) { sc = mm + logf(dd); g_ctr_lg = 0u; }
    }
    __syncthreads();
    float c = sc;
    for (int v = tid; v < VOC; v += TBV) out[v] -= c;
}

// ---------------- launch ----------------
extern "C" void kernel_launch(void* const* d_in, const int* in_sizes, int n_in,
                              void* d_out, int out_size) {
    const int*   query = (const int*)  d_in[0];
    const int*   story = (const int*)  d_in[1];
    const float* Wa    = (const float*)d_in[2];
    const float* Wc    = (const float*)d_in[3];
    const float* Wb    = (const float*)d_in[4];
    const float* Wt_w  = (const float*)d_in[5];
    const float* Wt_b  = (const float*)d_in[6];
    const float* H_w   = (const float*)d_in[7];
    const float* H_b   = (const float*)d_in[8];
    const float* wout  = (const float*)d_in[9];
    const float* TA    = (const float*)d_in[10];
    const float* TC    = (const float*)d_in[11];
    float* out = (float*)d_out;

    k_u0<<<1, EMB>>>(query, Wb);

    for (int h = 0; h < N_HOPS; h++) {
        k_pv    <<<NBV, TBV>>>(Wa, TA);
        k_hopmem<<<NBM, TBM>>>(story, TC);
        k_wo    <<<NBV, TBV>>>(Wc, Wt_w, Wt_b, H_w, H_b);
    }

    k_logits<<<NBV, TBV>>>(wout, out);
}